// round 2
// baseline (speedup 1.0000x reference)
#include <cuda_runtime.h>
#include <cstddef>

#define N_ENT   100000
#define N_REL   18
#define N_TRI   600000
#define BSZ     64
#define MAXQ    32
#define DH      300
#define D_CLS   1024

// ---------------- scratch (static device globals: no allocation) -------------
__device__ float g_eA[(size_t)N_ENT * BSZ];
__device__ float g_eB[(size_t)N_ENT * BSZ];
__device__ float g_lastc[BSZ * DH];          // 19200
__device__ float g_relT[N_REL * BSZ];        // [rel][b]
__device__ float g_predAcc[BSZ * DH + BSZ];  // 19200 accum + 64 row-sums
__device__ float g_h[BSZ * D_CLS];

// ---------------- helpers ----------------------------------------------------
__device__ __forceinline__ float warp_sum(float v) {
    #pragma unroll
    for (int o = 16; o; o >>= 1) v += __shfl_xor_sync(0xffffffffu, v, o);
    return v;
}
__device__ __forceinline__ float warp_max(float v) {
    #pragma unroll
    for (int o = 16; o; o >>= 1) v = fmaxf(v, __shfl_xor_sync(0xffffffffu, v, o));
    return v;
}
__device__ __forceinline__ unsigned long long pk2(float lo, float hi) {
    unsigned long long r;
    asm("mov.b64 %0, {%1, %2};" : "=l"(r) : "f"(lo), "f"(hi));
    return r;
}
__device__ __forceinline__ float2 upk(unsigned long long v) {
    float2 r;
    asm("mov.b64 {%0, %1}, %2;" : "=f"(r.x), "=f"(r.y) : "l"(v));
    return r;
}
// packed dual-FMA: d = a*b + d  (two f32 lanes per instruction)
__device__ __forceinline__ void fma2(unsigned long long& d, unsigned long long a,
                                     unsigned long long b) {
    asm("fma.rn.f32x2 %0, %1, %2, %0;" : "+l"(d) : "l"(a), "l"(b));
}

// ---------------- K0: transpose e_s [64,N_ENT] -> eT [N_ENT,64] --------------
__global__ void transpose_kernel(const float* __restrict__ in, float* __restrict__ out) {
    __shared__ float tile[32][33];
    int tx = threadIdx.x, ty = threadIdx.y;
    int o_in = blockIdx.x * 32 + tx;
    int b_in = blockIdx.y * 32 + ty;
    tile[ty][tx] = in[(size_t)b_in * N_ENT + o_in];
    __syncthreads();
    int o_out = blockIdx.x * 32 + ty;
    int b_out = blockIdx.y * 32 + tx;
    out[(size_t)o_out * BSZ + b_out] = tile[tx][ty];
}

// ---------------- zero helper ------------------------------------------------
__global__ void zero4_kernel(float4* __restrict__ p, int n4) {
    int i = blockIdx.x * blockDim.x + threadIdx.x;
    if (i < n4) p[i] = make_float4(0.f, 0.f, 0.f, 0.f);
}

// ---------------- per-step dense math (one block per batch row) --------------
__global__ void step_kernel(const float* __restrict__ qwh, const float* __restrict__ qemb,
                            const float* __restrict__ Wstep, const float* __restrict__ bstep,
                            const float* __restrict__ Wcq, const float* __restrict__ bcq,
                            const float* __restrict__ Wca, const float* __restrict__ bca,
                            const float* __restrict__ Wrel, const float* __restrict__ brel,
                            float* __restrict__ lastc, float* __restrict__ relT, int t) {
    __shared__ float s_qe[DH], s_lc[DH], s_qt[DH], s_cw[DH];
    __shared__ float s_log[MAXQ], s_dist[MAXQ];
    int b = blockIdx.x, tid = threadIdx.x;

    if (tid < DH) {
        s_qe[tid] = qemb[b * DH + tid];
        s_lc[tid] = lastc[b * DH + tid];
    }
    __syncthreads();

    // q_t = tanh(q_emb @ W_step[t] + b_step[t])
    if (tid < DH) {
        const float* W = Wstep + t * DH * DH;
        float acc = bstep[t * DH + tid];
        for (int k = 0; k < DH; ++k) acc = fmaf(s_qe[k], W[k * DH + tid], acc);
        s_qt[tid] = tanhf(acc);
    }
    __syncthreads();

    // cq = [last_c, q_t] @ W_cq + b_cq ; keep only cq*W_ca
    if (tid < DH) {
        float acc = bcq[tid];
        for (int k = 0; k < DH; ++k) acc = fmaf(s_lc[k], Wcq[k * DH + tid], acc);
        for (int k = 0; k < DH; ++k) acc = fmaf(s_qt[k], Wcq[(DH + k) * DH + tid], acc);
        s_cw[tid] = acc * Wca[tid];
    }
    __syncthreads();

    // word logits (10 warps cover 32 q values)
    {
        int w = tid >> 5, lane = tid & 31;
        for (int q = w; q < MAXQ; q += 10) {
            const float* row = qwh + ((size_t)b * MAXQ + q) * DH;
            float acc = 0.f;
            for (int d = lane; d < DH; d += 32) acc = fmaf(s_cw[d], row[d], acc);
            acc = warp_sum(acc);
            if (lane == 0) s_log[q] = acc + bca[0];
        }
    }
    __syncthreads();

    // softmax over 32 words (warp 0)
    if (tid < 32) {
        float v = s_log[tid];
        float m = warp_max(v);
        float e = expf(v - m);
        float s = warp_sum(e);
        s_dist[tid] = e / s;
    }
    __syncthreads();

    // last_c = dist @ q_word_h
    if (tid < DH) {
        const float* base = qwh + (size_t)b * MAXQ * DH + tid;
        float acc = 0.f;
        #pragma unroll
        for (int q = 0; q < MAXQ; ++q) acc = fmaf(s_dist[q], base[q * DH], acc);
        s_lc[tid] = acc;
        lastc[b * DH + tid] = acc;
    }
    __syncthreads();

    // rel_dist = softmax(last_c @ W_rel + b_rel); store transposed [rel][b]
    if (tid < 32) {
        float val = -1e30f;
        if (tid < N_REL) {
            float acc = brel[tid];
            for (int d = 0; d < DH; ++d) acc = fmaf(s_lc[d], Wrel[d * N_REL + tid], acc);
            val = acc;
        }
        float m = warp_max(val);
        float e = (tid < N_REL) ? expf(val - m) : 0.f;
        float s = warp_sum(e);
        if (tid < N_REL) relT[tid * BSZ + b] = e / s;
    }
}

// ---------------- follow: scatter over triples (16 threads / triple) ---------
__global__ void scatter_kernel(const float* __restrict__ eCur, const float* __restrict__ relT,
                               const int* __restrict__ subj, const int* __restrict__ rel,
                               const int* __restrict__ obj, float* __restrict__ eNext) {
    int gid = blockIdx.x * blockDim.x + threadIdx.x;
    int t = gid >> 4;
    int p = (gid & 15) << 2;
    int s = __ldg(subj + t), r = __ldg(rel + t), o = __ldg(obj + t);
    const float4 ev = *reinterpret_cast<const float4*>(eCur + (size_t)s * BSZ + p);
    const float4 rv = *reinterpret_cast<const float4*>(relT + r * BSZ + p);
    float4 x;
    x.x = ev.x * rv.x; x.y = ev.y * rv.y; x.z = ev.z * rv.z; x.w = ev.w * rv.w;
    float* dst = eNext + (size_t)o * BSZ + p;
    asm volatile("red.global.add.v4.f32 [%0], {%1, %2, %3, %4};"
                 :: "l"(dst), "f"(x.x), "f"(x.y), "f"(x.z), "f"(x.w) : "memory");
}

// ---------------- GEMM1: predAcc[b,d] = sum_o eT[o,b]*emb[o,d]; also row sums
__global__ void gemm1_kernel(const float* __restrict__ eT, const float* __restrict__ emb,
                             float* __restrict__ predAcc) {
    constexpr int EPB = 676;  // ceil(100000/148)
    __shared__ alignas(16) float s_e[8][BSZ];
    __shared__ unsigned long long s_embd[8][DH];
    int tid = threadIdx.x;
    int bp = tid & 31;   // batch pair: b0 = 2*bp
    int g  = tid >> 5;   // 0..24, owns 12 d's
    int o0 = blockIdx.x * EPB;
    int oend = min(o0 + EPB, N_ENT);

    unsigned long long acc[12];
    #pragma unroll
    for (int j = 0; j < 12; ++j) acc[j] = 0ull;
    float sa = 0.f, sb = 0.f;

    for (int oc = o0; oc < o0 + EPB; oc += 8) {
        if (tid < 512) {
            int i = tid >> 6, b = tid & 63;
            int o = oc + i;
            s_e[i][b] = (o < oend) ? eT[(size_t)o * BSZ + b] : 0.f;
        }
        for (int idx = tid; idx < 8 * DH; idx += 800) {
            int i = idx / DH, d = idx % DH;
            int o = oc + i;
            float v = (o < oend) ? emb[(size_t)o * DH + d] : 0.f;
            s_embd[i][d] = pk2(v, v);
        }
        __syncthreads();
        #pragma unroll
        for (int i = 0; i < 8; ++i) {
            unsigned long long ep =
                reinterpret_cast<const unsigned long long*>(&s_e[i][0])[bp];
            #pragma unroll
            for (int j = 0; j < 12; ++j) fma2(acc[j], ep, s_embd[i][g * 12 + j]);
            if (g == 0) { float2 e2 = upk(ep); sa += e2.x; sb += e2.y; }
        }
        __syncthreads();
    }
    int b0 = 2 * bp;
    #pragma unroll
    for (int j = 0; j < 12; ++j) {
        float2 a = upk(acc[j]);
        int d = g * 12 + j;
        atomicAdd(&predAcc[b0 * DH + d], a.x);
        atomicAdd(&predAcc[(b0 + 1) * DH + d], a.y);
    }
    if (g == 0) {
        atomicAdd(&predAcc[BSZ * DH + b0], sa);
        atomicAdd(&predAcc[BSZ * DH + b0 + 1], sb);
    }
}

// ---------------- h = relu(normed_pred @ W_e1 + b_e1) ------------------------
__global__ void h_kernel(const float* __restrict__ predAcc, const float* __restrict__ We1,
                         const float* __restrict__ be1, float* __restrict__ h) {
    __shared__ float s_p[DH];
    int b = blockIdx.x, tid = threadIdx.x;
    float inv = 1.f / (predAcc[BSZ * DH + b] + 1e-6f);
    for (int i = tid; i < DH; i += 256) s_p[i] = predAcc[b * DH + i] * inv;
    __syncthreads();
    int d = blockIdx.y * 256 + tid;
    float acc = be1[d];
    for (int k = 0; k < DH; ++k) acc = fmaf(s_p[k], We1[k * D_CLS + d], acc);
    h[b * D_CLS + d] = fmaxf(acc, 0.f);
}

// ---------------- GEMM2: out[64,100000] = h[64,1024] @ W_e2 + b_e2 -----------
__global__ void gemm2_kernel(const float* __restrict__ h, const float* __restrict__ We2,
                             const float* __restrict__ be2, float* __restrict__ out) {
    __shared__ unsigned long long s_h[64][BSZ];  // duplicated-pair h values
    int tid = threadIdx.x;
    int nq = tid & 31;       // n group
    int bq = tid >> 5;       // 0..15 -> owns b = 4*bq .. 4*bq+3
    int n0 = blockIdx.x * 256;
    int nA = n0 + nq * 4;
    int nB = nA + 128;
    bool v1 = (nB + 4 <= N_ENT);

    unsigned long long acc[4][4];
    #pragma unroll
    for (int j = 0; j < 4; ++j)
        #pragma unroll
        for (int s = 0; s < 4; ++s) acc[j][s] = 0ull;

    for (int kc = 0; kc < 16; ++kc) {
        int k0 = kc * 64;
        for (int i = tid; i < 64 * BSZ; i += 512) {
            int kk = i & 63, b = i >> 6;
            float v = h[b * D_CLS + k0 + kk];
            s_h[kk][b] = pk2(v, v);
        }
        __syncthreads();
        #pragma unroll 8
        for (int kk = 0; kk < 64; ++kk) {
            const float* wrow = We2 + (size_t)(k0 + kk) * N_ENT;
            ulonglong2 w0 = *reinterpret_cast<const ulonglong2*>(wrow + nA);
            ulonglong2 w1 = v1 ? *reinterpret_cast<const ulonglong2*>(wrow + nB)
                               : make_ulonglong2(0ull, 0ull);
            #pragma unroll
            for (int j = 0; j < 4; ++j) {
                unsigned long long hd = s_h[kk][bq * 4 + j];
                fma2(acc[j][0], w0.x, hd);
                fma2(acc[j][1], w0.y, hd);
                fma2(acc[j][2], w1.x, hd);
                fma2(acc[j][3], w1.y, hd);
            }
        }
        __syncthreads();
    }

    float4 bA = *reinterpret_cast<const float4*>(be2 + nA);
    float4 bB = v1 ? *reinterpret_cast<const float4*>(be2 + nB)
                   : make_float4(0.f, 0.f, 0.f, 0.f);
    #pragma unroll
    for (int j = 0; j < 4; ++j) {
        int b = bq * 4 + j;
        size_t base = (size_t)b * N_ENT;
        float2 a0 = upk(acc[j][0]), a1 = upk(acc[j][1]);
        float4 r0 = make_float4(a0.x + bA.x, a0.y + bA.y, a1.x + bA.z, a1.y + bA.w);
        *reinterpret_cast<float4*>(out + base + nA) = r0;
        if (v1) {
            float2 a2 = upk(acc[j][2]), a3 = upk(acc[j][3]);
            float4 r1 = make_float4(a2.x + bB.x, a2.y + bB.y, a3.x + bB.z, a3.y + bB.w);
            *reinterpret_cast<float4*>(out + base + nB) = r1;
        }
    }
}

// ---------------- launch -----------------------------------------------------
extern "C" void kernel_launch(void* const* d_in, const int* in_sizes, int n_in,
                              void* d_out, int out_size) {
    const float* qwh   = (const float*)d_in[0];
    const float* qemb  = (const float*)d_in[1];
    const float* e_s   = (const float*)d_in[2];
    const float* Wstep = (const float*)d_in[3];
    const float* bstep = (const float*)d_in[4];
    const float* Wcq   = (const float*)d_in[5];
    const float* bcq   = (const float*)d_in[6];
    const float* Wca   = (const float*)d_in[7];
    const float* bca   = (const float*)d_in[8];
    const float* Wrel  = (const float*)d_in[9];
    const float* brel  = (const float*)d_in[10];
    const float* emb   = (const float*)d_in[11];
    const float* We1   = (const float*)d_in[12];
    const float* be1   = (const float*)d_in[13];
    const float* We2   = (const float*)d_in[14];
    const float* be2   = (const float*)d_in[15];
    const int*   subj  = (const int*)d_in[16];
    const int*   rel   = (const int*)d_in[17];
    const int*   obj   = (const int*)d_in[18];
    float* out = (float*)d_out;

    float *eA, *eB, *lastc, *relT, *predAcc, *h;
    cudaGetSymbolAddress((void**)&eA, g_eA);
    cudaGetSymbolAddress((void**)&eB, g_eB);
    cudaGetSymbolAddress((void**)&lastc, g_lastc);
    cudaGetSymbolAddress((void**)&relT, g_relT);
    cudaGetSymbolAddress((void**)&predAcc, g_predAcc);
    cudaGetSymbolAddress((void**)&h, g_h);

    transpose_kernel<<<dim3(N_ENT / 32, BSZ / 32), dim3(32, 32)>>>(e_s, eA);
    zero4_kernel<<<(BSZ * DH / 4 + 255) / 256, 256>>>((float4*)lastc, BSZ * DH / 4);

    float* cur = eA;
    float* nxt = eB;
    for (int t = 0; t < 3; ++t) {
        step_kernel<<<BSZ, 320>>>(qwh, qemb, Wstep, bstep, Wcq, bcq, Wca, bca,
                                  Wrel, brel, lastc, relT, t);
        zero4_kernel<<<(N_ENT * BSZ / 4) / 256, 256>>>((float4*)nxt, N_ENT * BSZ / 4);
        scatter_kernel<<<(N_TRI * 16) / 256, 256>>>(cur, relT, subj, rel, obj, nxt);
        float* tmp = cur; cur = nxt; nxt = tmp;
    }

    zero4_kernel<<<((BSZ * DH + BSZ) / 4 + 255) / 256, 256>>>((float4*)predAcc,
                                                              (BSZ * DH + BSZ) / 4);
    gemm1_kernel<<<148, 800>>>(cur, emb, predAcc);
    h_kernel<<<dim3(BSZ, D_CLS / 256), 256>>>(predAcc, We1, be1, h);
    gemm2_kernel<<<(N_ENT + 255) / 256, 512>>>(h, We2, be2, out);
}

// round 3
// speedup vs baseline: 1.0243x; 1.0243x over previous
#include <cuda_runtime.h>
#include <cstddef>

#define N_ENT   100000
#define N_REL   18
#define N_TRI   600000
#define BSZ     64
#define MAXQ    32
#define DH      300
#define D_CLS   1024

// ---------------- scratch (static device globals: no allocation) -------------
__device__ float g_eA[(size_t)N_ENT * BSZ];
__device__ float g_eB[(size_t)N_ENT * BSZ];
__device__ float g_lastc[BSZ * DH];
__device__ float g_relT[N_REL * BSZ];
__device__ float g_predAcc[BSZ * DH + BSZ];
__device__ float g_h[BSZ * D_CLS];
// CSR-by-object index
__device__ int g_cnt[N_ENT + 1];
__device__ int g_off[N_ENT + 1];
__device__ int g_pos[N_ENT];
__device__ int g_sS[N_TRI];
__device__ int g_rS[N_TRI];

// ---------------- helpers ----------------------------------------------------
__device__ __forceinline__ float warp_sum(float v) {
    #pragma unroll
    for (int o = 16; o; o >>= 1) v += __shfl_xor_sync(0xffffffffu, v, o);
    return v;
}
__device__ __forceinline__ float warp_max(float v) {
    #pragma unroll
    for (int o = 16; o; o >>= 1) v = fmaxf(v, __shfl_xor_sync(0xffffffffu, v, o));
    return v;
}
__device__ __forceinline__ unsigned long long pk2(float lo, float hi) {
    unsigned long long r;
    asm("mov.b64 %0, {%1, %2};" : "=l"(r) : "f"(lo), "f"(hi));
    return r;
}
__device__ __forceinline__ float2 upk(unsigned long long v) {
    float2 r;
    asm("mov.b64 {%0, %1}, %2;" : "=f"(r.x), "=f"(r.y) : "l"(v));
    return r;
}
__device__ __forceinline__ void fma2(unsigned long long& d, unsigned long long a,
                                     unsigned long long b) {
    asm("fma.rn.f32x2 %0, %1, %2, %0;" : "+l"(d) : "l"(a), "l"(b));
}

// ---------------- K1: transpose e_s [64,N_ENT] -> eT [N_ENT,64]; zero cnt ----
__global__ void transpose_kernel(const float* __restrict__ in, float* __restrict__ out,
                                 int* __restrict__ cnt) {
    __shared__ float tile[32][33];
    int tx = threadIdx.x, ty = threadIdx.y;
    int o_in = blockIdx.x * 32 + tx;
    int b_in = blockIdx.y * 32 + ty;
    tile[ty][tx] = in[(size_t)b_in * N_ENT + o_in];
    // piggyback: zero the histogram counters
    int gid = (blockIdx.y * gridDim.x + blockIdx.x) * 1024 + ty * 32 + tx;
    if (gid <= N_ENT) cnt[gid] = 0;
    __syncthreads();
    int o_out = blockIdx.x * 32 + ty;
    int b_out = blockIdx.y * 32 + tx;
    out[(size_t)o_out * BSZ + b_out] = tile[tx][ty];
}

// ---------------- K2: histogram of obj ---------------------------------------
__global__ void hist_kernel(const int* __restrict__ obj, int* __restrict__ cnt) {
    int t = blockIdx.x * blockDim.x + threadIdx.x;
    if (t < N_TRI) atomicAdd(&cnt[obj[t]], 1);
}

// ---------------- K3: single-block exclusive scan + init pos + zero predAcc --
__global__ void scan_kernel(const int* __restrict__ cnt, int* __restrict__ off,
                            int* __restrict__ pos, float* __restrict__ predAcc) {
    constexpr int CH = (N_ENT + 1023) / 1024;  // 98
    __shared__ int s_part[1024];
    int tid = threadIdx.x;
    int base = tid * CH;
    int sum = 0;
    #pragma unroll 4
    for (int i = 0; i < CH; ++i) {
        int idx = base + i;
        if (idx < N_ENT) sum += cnt[idx];
    }
    s_part[tid] = sum;
    __syncthreads();
    // inclusive Hillis-Steele scan
    #pragma unroll
    for (int d = 1; d < 1024; d <<= 1) {
        int v = (tid >= d) ? s_part[tid - d] : 0;
        __syncthreads();
        s_part[tid] += v;
        __syncthreads();
    }
    int run = s_part[tid] - sum;  // exclusive prefix
    for (int i = 0; i < CH; ++i) {
        int idx = base + i;
        if (idx < N_ENT) {
            int c = cnt[idx];
            off[idx] = run;
            pos[idx] = run;
            run += c;
        }
    }
    if (tid == 1023) off[N_ENT] = run;
    for (int i = tid; i < BSZ * DH + BSZ; i += 1024) predAcc[i] = 0.f;
}

// ---------------- K4: scatter triples into CSR order -------------------------
__global__ void scatteridx_kernel(const int* __restrict__ subj, const int* __restrict__ rel,
                                  const int* __restrict__ obj, int* __restrict__ pos,
                                  int* __restrict__ sS, int* __restrict__ rS) {
    int t = blockIdx.x * blockDim.x + threadIdx.x;
    if (t < N_TRI) {
        int o = obj[t];
        int p = atomicAdd(&pos[o], 1);
        sS[p] = subj[t];
        rS[p] = rel[t];
    }
}

// ---------------- per-step dense math (one block per batch row) --------------
__global__ void step_kernel(const float* __restrict__ qwh, const float* __restrict__ qemb,
                            const float* __restrict__ Wstep, const float* __restrict__ bstep,
                            const float* __restrict__ Wcq, const float* __restrict__ bcq,
                            const float* __restrict__ Wca, const float* __restrict__ bca,
                            const float* __restrict__ Wrel, const float* __restrict__ brel,
                            float* __restrict__ lastc, float* __restrict__ relT, int t) {
    __shared__ float s_qe[DH], s_lc[DH], s_qt[DH], s_cw[DH];
    __shared__ float s_log[MAXQ], s_dist[MAXQ];
    int b = blockIdx.x, tid = threadIdx.x;

    if (tid < DH) {
        s_qe[tid] = qemb[b * DH + tid];
        s_lc[tid] = (t == 0) ? 0.f : lastc[b * DH + tid];
    }
    __syncthreads();

    if (tid < DH) {
        const float* W = Wstep + t * DH * DH;
        float acc = bstep[t * DH + tid];
        for (int k = 0; k < DH; ++k) acc = fmaf(s_qe[k], W[k * DH + tid], acc);
        s_qt[tid] = tanhf(acc);
    }
    __syncthreads();

    if (tid < DH) {
        float acc = bcq[tid];
        if (t != 0)
            for (int k = 0; k < DH; ++k) acc = fmaf(s_lc[k], Wcq[k * DH + tid], acc);
        for (int k = 0; k < DH; ++k) acc = fmaf(s_qt[k], Wcq[(DH + k) * DH + tid], acc);
        s_cw[tid] = acc * Wca[tid];
    }
    __syncthreads();

    {
        int w = tid >> 5, lane = tid & 31;
        for (int q = w; q < MAXQ; q += 10) {
            const float* row = qwh + ((size_t)b * MAXQ + q) * DH;
            float acc = 0.f;
            for (int d = lane; d < DH; d += 32) acc = fmaf(s_cw[d], row[d], acc);
            acc = warp_sum(acc);
            if (lane == 0) s_log[q] = acc + bca[0];
        }
    }
    __syncthreads();

    if (tid < 32) {
        float v = s_log[tid];
        float m = warp_max(v);
        float e = expf(v - m);
        float s = warp_sum(e);
        s_dist[tid] = e / s;
    }
    __syncthreads();

    if (tid < DH) {
        const float* base = qwh + (size_t)b * MAXQ * DH + tid;
        float acc = 0.f;
        #pragma unroll
        for (int q = 0; q < MAXQ; ++q) acc = fmaf(s_dist[q], base[q * DH], acc);
        s_lc[tid] = acc;
        lastc[b * DH + tid] = acc;
    }
    __syncthreads();

    if (tid < 32) {
        float val = -1e30f;
        if (tid < N_REL) {
            float acc = brel[tid];
            for (int d = 0; d < DH; ++d) acc = fmaf(s_lc[d], Wrel[d * N_REL + tid], acc);
            val = acc;
        }
        float m = warp_max(val);
        float e = (tid < N_REL) ? expf(val - m) : 0.f;
        float s = warp_sum(e);
        if (tid < N_REL) relT[tid * BSZ + b] = e / s;
    }
}

// ---------------- follow via CSR: warp per object, no atomics ----------------
__global__ void follow_kernel(const float* __restrict__ eCur, const float* __restrict__ relT,
                              const int* __restrict__ off, const int* __restrict__ sS,
                              const int* __restrict__ rS, float* __restrict__ eNext) {
    int o = blockIdx.x * 8 + (threadIdx.x >> 5);
    int lane = threadIdx.x & 31;
    int beg = __ldg(off + o), end = __ldg(off + o + 1);
    float2 acc = make_float2(0.f, 0.f);
    for (int t = beg; t < end; ++t) {
        int s = __ldg(sS + t), r = __ldg(rS + t);
        float2 e = *reinterpret_cast<const float2*>(eCur + (size_t)s * BSZ + 2 * lane);
        float2 rv = *reinterpret_cast<const float2*>(relT + r * BSZ + 2 * lane);
        acc.x = fmaf(e.x, rv.x, acc.x);
        acc.y = fmaf(e.y, rv.y, acc.y);
    }
    *reinterpret_cast<float2*>(eNext + (size_t)o * BSZ + 2 * lane) = acc;
}

// ---------------- GEMM1: predAcc[b,d] = sum_o eT[o,b]*emb[o,d]; + row sums ---
__global__ void gemm1_kernel(const float* __restrict__ eT, const float* __restrict__ emb,
                             float* __restrict__ predAcc) {
    constexpr int EPB = 676;  // ceil(100000/148)
    __shared__ alignas(16) float s_e[8][BSZ];
    __shared__ unsigned long long s_embd[8][DH];
    int tid = threadIdx.x;
    int bp = tid & 31;
    int g  = tid >> 5;
    int o0 = blockIdx.x * EPB;
    int oend = min(o0 + EPB, N_ENT);

    unsigned long long acc[12];
    #pragma unroll
    for (int j = 0; j < 12; ++j) acc[j] = 0ull;
    float sa = 0.f, sb = 0.f;

    for (int oc = o0; oc < o0 + EPB; oc += 8) {
        if (tid < 512) {
            int i = tid >> 6, b = tid & 63;
            int o = oc + i;
            s_e[i][b] = (o < oend) ? eT[(size_t)o * BSZ + b] : 0.f;
        }
        for (int idx = tid; idx < 8 * DH; idx += 800) {
            int i = idx / DH, d = idx % DH;
            int o = oc + i;
            float v = (o < oend) ? emb[(size_t)o * DH + d] : 0.f;
            s_embd[i][d] = pk2(v, v);
        }
        __syncthreads();
        #pragma unroll
        for (int i = 0; i < 8; ++i) {
            unsigned long long ep =
                reinterpret_cast<const unsigned long long*>(&s_e[i][0])[bp];
            #pragma unroll
            for (int j = 0; j < 12; ++j) fma2(acc[j], ep, s_embd[i][g * 12 + j]);
            if (g == 0) { float2 e2 = upk(ep); sa += e2.x; sb += e2.y; }
        }
        __syncthreads();
    }
    int b0 = 2 * bp;
    #pragma unroll
    for (int j = 0; j < 12; ++j) {
        float2 a = upk(acc[j]);
        int d = g * 12 + j;
        atomicAdd(&predAcc[b0 * DH + d], a.x);
        atomicAdd(&predAcc[(b0 + 1) * DH + d], a.y);
    }
    if (g == 0) {
        atomicAdd(&predAcc[BSZ * DH + b0], sa);
        atomicAdd(&predAcc[BSZ * DH + b0 + 1], sb);
    }
}

// ---------------- h = relu(normed_pred @ W_e1 + b_e1) ------------------------
__global__ void h_kernel(const float* __restrict__ predAcc, const float* __restrict__ We1,
                         const float* __restrict__ be1, float* __restrict__ h) {
    __shared__ float s_p[DH];
    int b = blockIdx.x, tid = threadIdx.x;
    float inv = 1.f / (predAcc[BSZ * DH + b] + 1e-6f);
    for (int i = tid; i < DH; i += 256) s_p[i] = predAcc[b * DH + i] * inv;
    __syncthreads();
    int d = blockIdx.y * 256 + tid;
    float acc = be1[d];
    for (int k = 0; k < DH; ++k) acc = fmaf(s_p[k], We1[k * D_CLS + d], acc);
    h[b * D_CLS + d] = fmaxf(acc, 0.f);
}

// ---------------- GEMM2: out[64,100000] = h[64,1024] @ W_e2 + b_e2 -----------
__global__ void gemm2_kernel(const float* __restrict__ h, const float* __restrict__ We2,
                             const float* __restrict__ be2, float* __restrict__ out) {
    __shared__ alignas(16) unsigned long long s_h[64][BSZ];
    int tid = threadIdx.x;
    int nq = tid & 31;
    int bq = tid >> 5;       // 0..15 -> owns b = 4*bq .. 4*bq+3
    int n0 = blockIdx.x * 256;
    int nA = n0 + nq * 4;
    int nB = nA + 128;
    bool v1 = (nB + 4 <= N_ENT);

    unsigned long long acc[4][4];
    #pragma unroll
    for (int j = 0; j < 4; ++j)
        #pragma unroll
        for (int s = 0; s < 4; ++s) acc[j][s] = 0ull;

    for (int kc = 0; kc < 16; ++kc) {
        int k0 = kc * 64;
        for (int i = tid; i < 64 * BSZ; i += 512) {
            int kk = i & 63, b = i >> 6;
            float v = h[b * D_CLS + k0 + kk];
            s_h[kk][b] = pk2(v, v);
        }
        __syncthreads();
        #pragma unroll 8
        for (int kk = 0; kk < 64; ++kk) {
            const float* wrow = We2 + (size_t)(k0 + kk) * N_ENT;
            ulonglong2 w0 = *reinterpret_cast<const ulonglong2*>(wrow + nA);
            ulonglong2 w1 = v1 ? *reinterpret_cast<const ulonglong2*>(wrow + nB)
                               : make_ulonglong2(0ull, 0ull);
            ulonglong2 hp = *reinterpret_cast<const ulonglong2*>(&s_h[kk][bq * 4]);
            ulonglong2 hq = *reinterpret_cast<const ulonglong2*>(&s_h[kk][bq * 4 + 2]);
            fma2(acc[0][0], w0.x, hp.x); fma2(acc[0][1], w0.y, hp.x);
            fma2(acc[0][2], w1.x, hp.x); fma2(acc[0][3], w1.y, hp.x);
            fma2(acc[1][0], w0.x, hp.y); fma2(acc[1][1], w0.y, hp.y);
            fma2(acc[1][2], w1.x, hp.y); fma2(acc[1][3], w1.y, hp.y);
            fma2(acc[2][0], w0.x, hq.x); fma2(acc[2][1], w0.y, hq.x);
            fma2(acc[2][2], w1.x, hq.x); fma2(acc[2][3], w1.y, hq.x);
            fma2(acc[3][0], w0.x, hq.y); fma2(acc[3][1], w0.y, hq.y);
            fma2(acc[3][2], w1.x, hq.y); fma2(acc[3][3], w1.y, hq.y);
        }
        __syncthreads();
    }

    float4 bA = *reinterpret_cast<const float4*>(be2 + nA);
    float4 bB = v1 ? *reinterpret_cast<const float4*>(be2 + nB)
                   : make_float4(0.f, 0.f, 0.f, 0.f);
    #pragma unroll
    for (int j = 0; j < 4; ++j) {
        int b = bq * 4 + j;
        size_t base = (size_t)b * N_ENT;
        float2 a0 = upk(acc[j][0]), a1 = upk(acc[j][1]);
        float4 r0 = make_float4(a0.x + bA.x, a0.y + bA.y, a1.x + bA.z, a1.y + bA.w);
        *reinterpret_cast<float4*>(out + base + nA) = r0;
        if (v1) {
            float2 a2 = upk(acc[j][2]), a3 = upk(acc[j][3]);
            float4 r1 = make_float4(a2.x + bB.x, a2.y + bB.y, a3.x + bB.z, a3.y + bB.w);
            *reinterpret_cast<float4*>(out + base + nB) = r1;
        }
    }
}

// ---------------- launch -----------------------------------------------------
extern "C" void kernel_launch(void* const* d_in, const int* in_sizes, int n_in,
                              void* d_out, int out_size) {
    const float* qwh   = (const float*)d_in[0];
    const float* qemb  = (const float*)d_in[1];
    const float* e_s   = (const float*)d_in[2];
    const float* Wstep = (const float*)d_in[3];
    const float* bstep = (const float*)d_in[4];
    const float* Wcq   = (const float*)d_in[5];
    const float* bcq   = (const float*)d_in[6];
    const float* Wca   = (const float*)d_in[7];
    const float* bca   = (const float*)d_in[8];
    const float* Wrel  = (const float*)d_in[9];
    const float* brel  = (const float*)d_in[10];
    const float* emb   = (const float*)d_in[11];
    const float* We1   = (const float*)d_in[12];
    const float* be1   = (const float*)d_in[13];
    const float* We2   = (const float*)d_in[14];
    const float* be2   = (const float*)d_in[15];
    const int*   subj  = (const int*)d_in[16];
    const int*   rel   = (const int*)d_in[17];
    const int*   obj   = (const int*)d_in[18];
    float* out = (float*)d_out;

    float *eA, *eB, *lastc, *relT, *predAcc, *h;
    int *cnt, *off, *pos, *sS, *rS;
    cudaGetSymbolAddress((void**)&eA, g_eA);
    cudaGetSymbolAddress((void**)&eB, g_eB);
    cudaGetSymbolAddress((void**)&lastc, g_lastc);
    cudaGetSymbolAddress((void**)&relT, g_relT);
    cudaGetSymbolAddress((void**)&predAcc, g_predAcc);
    cudaGetSymbolAddress((void**)&h, g_h);
    cudaGetSymbolAddress((void**)&cnt, g_cnt);
    cudaGetSymbolAddress((void**)&off, g_off);
    cudaGetSymbolAddress((void**)&pos, g_pos);
    cudaGetSymbolAddress((void**)&sS, g_sS);
    cudaGetSymbolAddress((void**)&rS, g_rS);

    // 1: transpose + zero hist counters
    transpose_kernel<<<dim3(N_ENT / 32, BSZ / 32), dim3(32, 32)>>>(e_s, eA, cnt);
    // 2: histogram by obj
    hist_kernel<<<(N_TRI + 255) / 256, 256>>>(obj, cnt);
    // 3: scan -> offsets (+ zero predAcc)
    scan_kernel<<<1, 1024>>>(cnt, off, pos, predAcc);
    // 4: CSR scatter
    scatteridx_kernel<<<(N_TRI + 255) / 256, 256>>>(subj, rel, obj, pos, sS, rS);

    float* cur = eA;
    float* nxt = eB;
    for (int t = 0; t < 3; ++t) {
        // 5/7/9: per-step dense math
        step_kernel<<<BSZ, 320>>>(qwh, qemb, Wstep, bstep, Wcq, bcq, Wca, bca,
                                  Wrel, brel, lastc, relT, t);
        // 6/8/10: follow (launch #6 is follow t=0 -> ncu capture target)
        follow_kernel<<<N_ENT / 8, 256>>>(cur, relT, off, sS, rS, nxt);
        float* tmp = cur; cur = nxt; nxt = tmp;
    }

    gemm1_kernel<<<148, 800>>>(cur, emb, predAcc);
    h_kernel<<<dim3(BSZ, D_CLS / 256), 256>>>(predAcc, We1, be1, h);
    gemm2_kernel<<<(N_ENT + 255) / 256, 512>>>(h, We2, be2, out);
}

// round 4
// speedup vs baseline: 1.0826x; 1.0568x over previous
#include <cuda_runtime.h>
#include <cstddef>

#define N_ENT   100000
#define N_REL   18
#define N_TRI   600000
#define BSZ     64
#define MAXQ    32
#define DH      300
#define D_CLS   1024
#define NB_CSR  148

// ---------------- scratch (static device globals: no allocation) -------------
__device__ float g_eA[(size_t)N_ENT * BSZ];
__device__ float g_eB[(size_t)N_ENT * BSZ];
__device__ float g_lastc[BSZ * DH];
__device__ float g_relT[N_REL * BSZ];
__device__ float g_predAcc[BSZ * DH + BSZ];
__device__ float g_h[BSZ * D_CLS];
// CSR-by-object index
__device__ int g_cnt[N_ENT + 1];
__device__ int g_off[N_ENT + 1];
__device__ int g_pos[N_ENT];
__device__ int2 g_srS[N_TRI];
__device__ int g_bsum[NB_CSR];
__device__ int g_bbase[NB_CSR];
__device__ unsigned g_barrier;   // monotonically-growing arrival counter

// ---------------- helpers ----------------------------------------------------
__device__ __forceinline__ float warp_sum(float v) {
    #pragma unroll
    for (int o = 16; o; o >>= 1) v += __shfl_xor_sync(0xffffffffu, v, o);
    return v;
}
__device__ __forceinline__ float warp_max(float v) {
    #pragma unroll
    for (int o = 16; o; o >>= 1) v = fmaxf(v, __shfl_xor_sync(0xffffffffu, v, o));
    return v;
}
__device__ __forceinline__ unsigned long long pk2(float lo, float hi) {
    unsigned long long r;
    asm("mov.b64 %0, {%1, %2};" : "=l"(r) : "f"(lo), "f"(hi));
    return r;
}
__device__ __forceinline__ float2 upk(unsigned long long v) {
    float2 r;
    asm("mov.b64 {%0, %1}, %2;" : "=f"(r.x), "=f"(r.y) : "l"(v));
    return r;
}
__device__ __forceinline__ void fma2(unsigned long long& d, unsigned long long a,
                                     unsigned long long b) {
    asm("fma.rn.f32x2 %0, %1, %2, %0;" : "+l"(d) : "l"(a), "l"(b));
}

// software grid barrier (all NB_CSR blocks co-resident; wrap-safe counter)
__device__ __forceinline__ void gsync() {
    __syncthreads();
    if (threadIdx.x == 0) {
        __threadfence();
        unsigned old = atomicAdd(&g_barrier, 1u);
        unsigned goal = old - (old % (unsigned)NB_CSR) + (unsigned)NB_CSR;
        while (true) {
            unsigned cur = *(volatile unsigned*)&g_barrier;
            if ((int)(cur - goal) >= 0) break;
        }
        __threadfence();
    }
    __syncthreads();
}

// ---------------- K1: transpose e_s [64,N_ENT] -> eT [N_ENT,64] --------------
__global__ void transpose_kernel(const float* __restrict__ in, float* __restrict__ out) {
    __shared__ float tile[32][33];
    int tx = threadIdx.x, ty = threadIdx.y;
    int o_in = blockIdx.x * 32 + tx;
    int b_in = blockIdx.y * 32 + ty;
    tile[ty][tx] = in[(size_t)b_in * N_ENT + o_in];
    __syncthreads();
    int o_out = blockIdx.x * 32 + ty;
    int b_out = blockIdx.y * 32 + tx;
    out[(size_t)o_out * BSZ + b_out] = tile[tx][ty];
}

// ---------------- K2: full CSR build in one persistent kernel ----------------
__global__ void __launch_bounds__(1024, 1)
csr_kernel(const int* __restrict__ subj, const int* __restrict__ rel,
           const int* __restrict__ obj, int* __restrict__ cnt,
           int* __restrict__ off, int* __restrict__ pos,
           int2* __restrict__ srS, int* __restrict__ bsum, int* __restrict__ bbase,
           float* __restrict__ predAcc) {
    __shared__ int s_scan[1024];
    __shared__ int s_b[256];
    const int tid = threadIdx.x, bid = blockIdx.x;
    const int gtid = bid * 1024 + tid;
    const int gstride = NB_CSR * 1024;

    // --- A: zero counters + predAcc ---
    for (int i = gtid; i <= N_ENT; i += gstride) cnt[i] = 0;
    for (int i = gtid; i < BSZ * DH + BSZ; i += gstride) predAcc[i] = 0.f;
    gsync();

    // --- B: histogram of obj ---
    for (int t = gtid; t < N_TRI; t += gstride) atomicAdd(&cnt[obj[t]], 1);
    gsync();

    // --- C1: per-chunk block scan (chunk = 676 entities per block) ---
    constexpr int CH = (N_ENT + NB_CSR - 1) / NB_CSR;  // 676
    const int base = bid * CH;
    const int m = min(CH, N_ENT - base);
    int val = (tid < m) ? cnt[base + tid] : 0;
    s_scan[tid] = val;
    __syncthreads();
    #pragma unroll
    for (int d = 1; d < 1024; d <<= 1) {
        int v = (tid >= d) ? s_scan[tid - d] : 0;
        __syncthreads();
        s_scan[tid] += v;
        __syncthreads();
    }
    int excl = s_scan[tid] - val;
    if (tid == 1023) bsum[bid] = s_scan[1023];
    gsync();

    // --- C2: block 0 scans the 148 block sums ---
    if (bid == 0) {
        int bv = (tid < NB_CSR) ? bsum[tid] : 0;
        if (tid < 256) s_b[tid] = bv;
        __syncthreads();
        #pragma unroll
        for (int d = 1; d < 256; d <<= 1) {
            int v = 0;
            if (tid < 256 && tid >= d) v = s_b[tid - d];
            __syncthreads();
            if (tid < 256) s_b[tid] += v;
            __syncthreads();
        }
        if (tid < NB_CSR) bbase[tid] = s_b[tid] - bv;  // exclusive
    }
    gsync();

    // --- C3: write offsets ---
    int bb = bbase[bid];
    if (tid < m) {
        off[base + tid] = bb + excl;
        pos[base + tid] = bb + excl;
    }
    if (gtid == 0) off[N_ENT] = N_TRI;
    gsync();

    // --- D: scatter triples into CSR order ---
    for (int t = gtid; t < N_TRI; t += gstride) {
        int o = obj[t];
        int p = atomicAdd(&pos[o], 1);
        srS[p] = make_int2(subj[t], rel[t]);
    }
}

// ---------------- per-step dense math (one block per batch row) --------------
__global__ void step_kernel(const float* __restrict__ qwh, const float* __restrict__ qemb,
                            const float* __restrict__ Wstep, const float* __restrict__ bstep,
                            const float* __restrict__ Wcq, const float* __restrict__ bcq,
                            const float* __restrict__ Wca, const float* __restrict__ bca,
                            const float* __restrict__ Wrel, const float* __restrict__ brel,
                            float* __restrict__ lastc, float* __restrict__ relT, int t) {
    __shared__ float s_qe[DH], s_lc[DH], s_qt[DH], s_cw[DH];
    __shared__ float s_log[MAXQ], s_dist[MAXQ];
    int b = blockIdx.x, tid = threadIdx.x;

    if (tid < DH) {
        s_qe[tid] = qemb[b * DH + tid];
        s_lc[tid] = (t == 0) ? 0.f : lastc[b * DH + tid];
    }
    __syncthreads();

    if (tid < DH) {
        const float* W = Wstep + t * DH * DH;
        float acc = bstep[t * DH + tid];
        for (int k = 0; k < DH; ++k) acc = fmaf(s_qe[k], W[k * DH + tid], acc);
        s_qt[tid] = tanhf(acc);
    }
    __syncthreads();

    if (tid < DH) {
        float acc = bcq[tid];
        if (t != 0)
            for (int k = 0; k < DH; ++k) acc = fmaf(s_lc[k], Wcq[k * DH + tid], acc);
        for (int k = 0; k < DH; ++k) acc = fmaf(s_qt[k], Wcq[(DH + k) * DH + tid], acc);
        s_cw[tid] = acc * Wca[tid];
    }
    __syncthreads();

    {
        int w = tid >> 5, lane = tid & 31;
        for (int q = w; q < MAXQ; q += 10) {
            const float* row = qwh + ((size_t)b * MAXQ + q) * DH;
            float acc = 0.f;
            for (int d = lane; d < DH; d += 32) acc = fmaf(s_cw[d], row[d], acc);
            acc = warp_sum(acc);
            if (lane == 0) s_log[q] = acc + bca[0];
        }
    }
    __syncthreads();

    if (tid < 32) {
        float v = s_log[tid];
        float m = warp_max(v);
        float e = expf(v - m);
        float s = warp_sum(e);
        s_dist[tid] = e / s;
    }
    __syncthreads();

    if (tid < DH) {
        const float* base = qwh + (size_t)b * MAXQ * DH + tid;
        float acc = 0.f;
        #pragma unroll
        for (int q = 0; q < MAXQ; ++q) acc = fmaf(s_dist[q], base[q * DH], acc);
        s_lc[tid] = acc;
        lastc[b * DH + tid] = acc;
    }
    __syncthreads();

    if (tid < 32) {
        float val = -1e30f;
        if (tid < N_REL) {
            float acc = brel[tid];
            for (int d = 0; d < DH; ++d) acc = fmaf(s_lc[d], Wrel[d * N_REL + tid], acc);
            val = acc;
        }
        float m = warp_max(val);
        float e = (tid < N_REL) ? expf(val - m) : 0.f;
        float s = warp_sum(e);
        if (tid < N_REL) relT[tid * BSZ + b] = e / s;
    }
}

// ---------------- follow via CSR: warp per object, no atomics ----------------
__global__ void follow_kernel(const float* __restrict__ eCur, const float* __restrict__ relT,
                              const int* __restrict__ off, const int2* __restrict__ srS,
                              float* __restrict__ eNext) {
    int o = blockIdx.x * 8 + (threadIdx.x >> 5);
    int lane = threadIdx.x & 31;
    int beg = __ldg(off + o), end = __ldg(off + o + 1);
    float2 acc = make_float2(0.f, 0.f);
    for (int t = beg; t < end; ++t) {
        int2 sr = __ldg(srS + t);
        float2 e = *reinterpret_cast<const float2*>(eCur + (size_t)sr.x * BSZ + 2 * lane);
        float2 rv = *reinterpret_cast<const float2*>(relT + sr.y * BSZ + 2 * lane);
        acc.x = fmaf(e.x, rv.x, acc.x);
        acc.y = fmaf(e.y, rv.y, acc.y);
    }
    *reinterpret_cast<float2*>(eNext + (size_t)o * BSZ + 2 * lane) = acc;
}

// ---------------- GEMM1: predAcc[b,d] = sum_o eT[o,b]*emb[o,d]; + row sums ---
__global__ void gemm1_kernel(const float* __restrict__ eT, const float* __restrict__ emb,
                             float* __restrict__ predAcc) {
    constexpr int EPB = 676;
    __shared__ alignas(16) float s_e[8][BSZ];
    __shared__ unsigned long long s_embd[8][DH];
    int tid = threadIdx.x;
    int bp = tid & 31;
    int g  = tid >> 5;
    int o0 = blockIdx.x * EPB;
    int oend = min(o0 + EPB, N_ENT);

    unsigned long long acc[12];
    #pragma unroll
    for (int j = 0; j < 12; ++j) acc[j] = 0ull;
    float sa = 0.f, sb = 0.f;

    for (int oc = o0; oc < o0 + EPB; oc += 8) {
        if (tid < 512) {
            int i = tid >> 6, b = tid & 63;
            int o = oc + i;
            s_e[i][b] = (o < oend) ? eT[(size_t)o * BSZ + b] : 0.f;
        }
        for (int idx = tid; idx < 8 * DH; idx += 800) {
            int i = idx / DH, d = idx % DH;
            int o = oc + i;
            float v = (o < oend) ? emb[(size_t)o * DH + d] : 0.f;
            s_embd[i][d] = pk2(v, v);
        }
        __syncthreads();
        #pragma unroll
        for (int i = 0; i < 8; ++i) {
            unsigned long long ep =
                reinterpret_cast<const unsigned long long*>(&s_e[i][0])[bp];
            #pragma unroll
            for (int j = 0; j < 12; ++j) fma2(acc[j], ep, s_embd[i][g * 12 + j]);
            if (g == 0) { float2 e2 = upk(ep); sa += e2.x; sb += e2.y; }
        }
        __syncthreads();
    }
    int b0 = 2 * bp;
    #pragma unroll
    for (int j = 0; j < 12; ++j) {
        float2 a = upk(acc[j]);
        int d = g * 12 + j;
        atomicAdd(&predAcc[b0 * DH + d], a.x);
        atomicAdd(&predAcc[(b0 + 1) * DH + d], a.y);
    }
    if (g == 0) {
        atomicAdd(&predAcc[BSZ * DH + b0], sa);
        atomicAdd(&predAcc[BSZ * DH + b0 + 1], sb);
    }
}

// ---------------- h = relu(normed_pred @ W_e1 + b_e1) ------------------------
__global__ void h_kernel(const float* __restrict__ predAcc, const float* __restrict__ We1,
                         const float* __restrict__ be1, float* __restrict__ h) {
    __shared__ float s_p[DH];
    int b = blockIdx.x, tid = threadIdx.x;
    float inv = 1.f / (predAcc[BSZ * DH + b] + 1e-6f);
    for (int i = tid; i < DH; i += 256) s_p[i] = predAcc[b * DH + i] * inv;
    __syncthreads();
    int d = blockIdx.y * 256 + tid;
    float acc = be1[d];
    for (int k = 0; k < DH; ++k) acc = fmaf(s_p[k], We1[k * D_CLS + d], acc);
    h[b * D_CLS + d] = fmaxf(acc, 0.f);
}

// ---------------- GEMM2: out[64,100000] = h[64,1024] @ W_e2 + b_e2 -----------
__global__ void gemm2_kernel(const float* __restrict__ h, const float* __restrict__ We2,
                             const float* __restrict__ be2, float* __restrict__ out) {
    __shared__ alignas(16) unsigned long long s_h[64][BSZ];
    int tid = threadIdx.x;
    int nq = tid & 31;
    int bq = tid >> 5;
    int n0 = blockIdx.x * 256;
    int nA = n0 + nq * 4;
    int nB = nA + 128;
    bool v1 = (nB + 4 <= N_ENT);

    unsigned long long acc[4][4];
    #pragma unroll
    for (int j = 0; j < 4; ++j)
        #pragma unroll
        for (int s = 0; s < 4; ++s) acc[j][s] = 0ull;

    for (int kc = 0; kc < 16; ++kc) {
        int k0 = kc * 64;
        for (int i = tid; i < 64 * BSZ; i += 512) {
            int kk = i & 63, b = i >> 6;
            float v = h[b * D_CLS + k0 + kk];
            s_h[kk][b] = pk2(v, v);
        }
        __syncthreads();
        #pragma unroll 8
        for (int kk = 0; kk < 64; ++kk) {
            const float* wrow = We2 + (size_t)(k0 + kk) * N_ENT;
            ulonglong2 w0 = *reinterpret_cast<const ulonglong2*>(wrow + nA);
            ulonglong2 w1 = v1 ? *reinterpret_cast<const ulonglong2*>(wrow + nB)
                               : make_ulonglong2(0ull, 0ull);
            ulonglong2 hp = *reinterpret_cast<const ulonglong2*>(&s_h[kk][bq * 4]);
            ulonglong2 hq = *reinterpret_cast<const ulonglong2*>(&s_h[kk][bq * 4 + 2]);
            fma2(acc[0][0], w0.x, hp.x); fma2(acc[0][1], w0.y, hp.x);
            fma2(acc[0][2], w1.x, hp.x); fma2(acc[0][3], w1.y, hp.x);
            fma2(acc[1][0], w0.x, hp.y); fma2(acc[1][1], w0.y, hp.y);
            fma2(acc[1][2], w1.x, hp.y); fma2(acc[1][3], w1.y, hp.y);
            fma2(acc[2][0], w0.x, hq.x); fma2(acc[2][1], w0.y, hq.x);
            fma2(acc[2][2], w1.x, hq.x); fma2(acc[2][3], w1.y, hq.x);
            fma2(acc[3][0], w0.x, hq.y); fma2(acc[3][1], w0.y, hq.y);
            fma2(acc[3][2], w1.x, hq.y); fma2(acc[3][3], w1.y, hq.y);
        }
        __syncthreads();
    }

    float4 bA = *reinterpret_cast<const float4*>(be2 + nA);
    float4 bB = v1 ? *reinterpret_cast<const float4*>(be2 + nB)
                   : make_float4(0.f, 0.f, 0.f, 0.f);
    #pragma unroll
    for (int j = 0; j < 4; ++j) {
        int b = bq * 4 + j;
        size_t base = (size_t)b * N_ENT;
        float2 a0 = upk(acc[j][0]), a1 = upk(acc[j][1]);
        float4 r0 = make_float4(a0.x + bA.x, a0.y + bA.y, a1.x + bA.z, a1.y + bA.w);
        *reinterpret_cast<float4*>(out + base + nA) = r0;
        if (v1) {
            float2 a2 = upk(acc[j][2]), a3 = upk(acc[j][3]);
            float4 r1 = make_float4(a2.x + bB.x, a2.y + bB.y, a3.x + bB.z, a3.y + bB.w);
            *reinterpret_cast<float4*>(out + base + nB) = r1;
        }
    }
}

// ---------------- launch -----------------------------------------------------
extern "C" void kernel_launch(void* const* d_in, const int* in_sizes, int n_in,
                              void* d_out, int out_size) {
    const float* qwh   = (const float*)d_in[0];
    const float* qemb  = (const float*)d_in[1];
    const float* e_s   = (const float*)d_in[2];
    const float* Wstep = (const float*)d_in[3];
    const float* bstep = (const float*)d_in[4];
    const float* Wcq   = (const float*)d_in[5];
    const float* bcq   = (const float*)d_in[6];
    const float* Wca   = (const float*)d_in[7];
    const float* bca   = (const float*)d_in[8];
    const float* Wrel  = (const float*)d_in[9];
    const float* brel  = (const float*)d_in[10];
    const float* emb   = (const float*)d_in[11];
    const float* We1   = (const float*)d_in[12];
    const float* be1   = (const float*)d_in[13];
    const float* We2   = (const float*)d_in[14];
    const float* be2   = (const float*)d_in[15];
    const int*   subj  = (const int*)d_in[16];
    const int*   rel   = (const int*)d_in[17];
    const int*   obj   = (const int*)d_in[18];
    float* out = (float*)d_out;

    float *eA, *eB, *lastc, *relT, *predAcc, *h;
    int *cnt, *off, *pos, *bsum, *bbase;
    int2* srS;
    cudaGetSymbolAddress((void**)&eA, g_eA);
    cudaGetSymbolAddress((void**)&eB, g_eB);
    cudaGetSymbolAddress((void**)&lastc, g_lastc);
    cudaGetSymbolAddress((void**)&relT, g_relT);
    cudaGetSymbolAddress((void**)&predAcc, g_predAcc);
    cudaGetSymbolAddress((void**)&h, g_h);
    cudaGetSymbolAddress((void**)&cnt, g_cnt);
    cudaGetSymbolAddress((void**)&off, g_off);
    cudaGetSymbolAddress((void**)&pos, g_pos);
    cudaGetSymbolAddress((void**)&srS, g_srS);
    cudaGetSymbolAddress((void**)&bsum, g_bsum);
    cudaGetSymbolAddress((void**)&bbase, g_bbase);

    // 1: transpose
    transpose_kernel<<<dim3(N_ENT / 32, BSZ / 32), dim3(32, 32)>>>(e_s, eA);
    // 2: full CSR build (persistent, software grid sync) + predAcc zero
    csr_kernel<<<NB_CSR, 1024>>>(subj, rel, obj, cnt, off, pos, srS, bsum, bbase,
                                 predAcc);

    float* cur = eA;
    float* nxt = eB;
    for (int t = 0; t < 3; ++t) {
        // 3/5/7: per-step dense math
        step_kernel<<<BSZ, 320>>>(qwh, qemb, Wstep, bstep, Wcq, bcq, Wca, bca,
                                  Wrel, brel, lastc, relT, t);
        // 4/6/8: follow (launch #4 = follow t=0 -> ncu capture target)
        follow_kernel<<<N_ENT / 8, 256>>>(cur, relT, off, srS, nxt);
        float* tmp = cur; cur = nxt; nxt = tmp;
    }

    gemm1_kernel<<<148, 800>>>(cur, emb, predAcc);
    h_kernel<<<dim3(BSZ, D_CLS / 256), 256>>>(predAcc, We1, be1, h);
    gemm2_kernel<<<(N_ENT + 255) / 256, 512>>>(h, We2, be2, out);
}